// round 8
// baseline (speedup 1.0000x reference)
#include <cuda_runtime.h>
#include <cstdint>

// ---------------------------------------------------------------------------
// voxelization, scales (2,4,8,1). Quantization matches the JITted reference:
// XLA folds (dims*(p-lo))/(hi-lo) -> (p-lo) * RN(dims/(hi-lo)), and the folded
// f32 constants are EXACT: x/y: 512/102.4f->5.0f; z: 64/6.4f->10.0f; per-scale
// constants are exact power-of-2 multiples (2.5f,1.25f,...), so
// idx_s = idx_1 >> k exactly (floor(r/2)=floor(floor(r)/2)).
//   key = ((b*S + x)*S + y)*Z + z with ADDITION (carries like reference;
//         boundary idx==dims carries into the next field).
// Output: single FLOAT32 buffer, tight concat per scale:
//   full_coors [N,4] (b,x,y,z raw) | inv [N] | coors [M,4] (b,z,y,x)
// Dense bitmask + popcount prefix replaces sort/unique.
// ---------------------------------------------------------------------------

#define NMAX 2000000
// per-scale mask words padded past max carried key, in 8192-word blocks:
// scale2:65 scale4:9 scale8:2 scale1:513
#define TOTAL_WORDS 4825088   // (65+9+2+513)*8192

__device__ unsigned  g_mask[TOTAL_WORDS];            // 19.3 MB bitmasks
__device__ uint4     g_mp4[TOTAL_WORDS / 2];         // 38.6 MB {mask,prefix}
__device__ unsigned  g_pt[NMAX];                     // 8 MB packed b,x1,y1,z1
__device__ unsigned  g_blocksum[4 * 1024];
__device__ long long g_bases[12];                    // ELEMENT offs: fc,inv,coors
__device__ int       g_is64;                         // batch INPUT width only

__constant__ int      c_k[4]    = {1, 2, 3, 0};
__constant__ unsigned c_woff[4] = {0u, 532480u, 606208u, 622592u};
__constant__ int      c_nb[4]   = {65, 9, 2, 513};

// -------------------------------------------------- batch input width detect
__global__ void kdetect(const unsigned* __restrict__ bat) {
    // int64 batch values in [0,8): every odd 32-bit word is zero.
    unsigned acc = 0;
#pragma unroll
    for (int i = 1; i <= 16; i++) acc |= bat[2 * i + 1];
    g_is64 = (acc == 0u) ? 1 : 0;
}

// ---------------------------------------------------------------- zero masks
__global__ __launch_bounds__(256) void kzero() {
    unsigned i = blockIdx.x * 256u + threadIdx.x;
    if (i < TOTAL_WORDS / 4) ((uint4*)g_mask)[i] = make_uint4(0u, 0u, 0u, 0u);
}

// -------------------------------------- pass 1: packed point + bitmask set
__global__ __launch_bounds__(256) void k1(const float* __restrict__ pts,
                                          const void* __restrict__ bat,
                                          int n) {
    int i = blockIdx.x * 256 + threadIdx.x;
    if (i >= n) return;
    float px = pts[3 * i + 0];
    float py = pts[3 * i + 1];
    float pz = pts[3 * i + 2];
    unsigned b;
    if (g_is64) b = (unsigned)((const long long*)bat)[i];
    else        b = (unsigned)((const int*)bat)[i];
    // JIT/XLA-folded f32 semantics: trunc((p - lo) * RN(dims/(hi-lo)));
    // folded constants exact: 5.0f (x,y), 10.0f (z). idx may equal dims.
    unsigned x1 = (unsigned)(int)__fmul_rn(__fsub_rn(px, -51.2f), 5.0f);
    unsigned y1 = (unsigned)(int)__fmul_rn(__fsub_rn(py, -51.2f), 5.0f);
    unsigned z1 = (unsigned)(int)__fmul_rn(__fsub_rn(pz, -4.0f), 10.0f);
    g_pt[i] = (b << 27) | (x1 << 17) | (y1 << 7) | z1;   // raw, incl. boundary
#pragma unroll
    for (int s = 0; s < 4; s++) {
        int k = c_k[s], xb = 9 - k, zb = 6 - k;
        // ARITHMETIC packing: carries propagate exactly like reference int64
        unsigned key = (((((b << xb) + (x1 >> k)) << xb) + (y1 >> k)) << zb)
                       + (z1 >> k);
        unsigned w = c_woff[s] + (key >> 5), bm = 1u << (key & 31);
        if (!(g_mask[w] & bm)) atomicOr(&g_mask[w], bm);  // stale=subset: safe
    }
}

// ----------------------------------------- P1: per-block popcount partial sum
__global__ __launch_bounds__(256) void p1(int s) {
    unsigned base = c_woff[s] + blockIdx.x * 8192u + threadIdx.x * 32u;
    const uint4* src = (const uint4*)(g_mask + base);
    unsigned sum = 0;
#pragma unroll
    for (int j = 0; j < 8; j++) {
        uint4 v = src[j];
        sum += __popc(v.x) + __popc(v.y) + __popc(v.z) + __popc(v.w);
    }
    __shared__ unsigned sh[256];
    sh[threadIdx.x] = sum;
    __syncthreads();
    for (int o = 128; o; o >>= 1) {
        if (threadIdx.x < (unsigned)o) sh[threadIdx.x] += sh[threadIdx.x + o];
        __syncthreads();
    }
    if (threadIdx.x == 0) g_blocksum[s * 1024 + blockIdx.x] = sh[0];
}

// --------- P2: scan block sums per scale, compute M + section ELEMENT bases
__global__ __launch_bounds__(1024) void p2(int n) {
    __shared__ unsigned sh[1024];
    __shared__ unsigned Mtot[4];
    int tid = threadIdx.x;
    for (int s = 0; s < 4; s++) {
        int nb = c_nb[s];
        unsigned v = (tid < nb) ? g_blocksum[s * 1024 + tid] : 0u;
        sh[tid] = v;
        __syncthreads();
        for (int o = 1; o < 1024; o <<= 1) {
            unsigned t = (tid >= o) ? sh[tid - o] : 0u;
            __syncthreads();
            sh[tid] += t;
            __syncthreads();
        }
        unsigned incl = sh[tid];
        if (tid < nb) g_blocksum[s * 1024 + tid] = incl - v;  // exclusive
        if (tid == nb - 1) Mtot[s] = incl;
        __syncthreads();
    }
    if (tid == 0) {
        long long base = 0;  // float-element offsets into d_out
        for (int s = 0; s < 4; s++) {
            g_bases[3 * s + 0] = base;                 // full_coors (4n)
            g_bases[3 * s + 1] = base + 4ll * n;       // inv (n)
            g_bases[3 * s + 2] = base + 5ll * n;       // coors (4M)
            base += 5ll * n + 4ll * (long long)Mtot[s];
        }
    }
}

// ----------------- P3: word-level exclusive prefix, write {mask,prefix} pairs
__global__ __launch_bounds__(256) void p3(int s) {
    int tid = threadIdx.x;
    unsigned woff = c_woff[s];
    unsigned wbase = blockIdx.x * 8192u + tid * 32u;
    const uint4* src = (const uint4*)(g_mask + woff + wbase);
    uint4 v[8];
    unsigned sum = 0;
#pragma unroll
    for (int j = 0; j < 8; j++) v[j] = src[j];
#pragma unroll
    for (int j = 0; j < 8; j++)
        sum += __popc(v[j].x) + __popc(v[j].y) + __popc(v[j].z) + __popc(v[j].w);
    __shared__ unsigned sh[256];
    sh[tid] = sum;
    __syncthreads();
    for (int o = 1; o < 256; o <<= 1) {
        unsigned t = (tid >= o) ? sh[tid - o] : 0u;
        __syncthreads();
        sh[tid] += t;
        __syncthreads();
    }
    unsigned run = g_blocksum[s * 1024 + blockIdx.x] + sh[tid] - sum;
    uint4* dst = (uint4*)((uint2*)g_mp4 + (woff + wbase));
#pragma unroll
    for (int j = 0; j < 8; j++) {
        unsigned w0 = v[j].x, w1 = v[j].y, w2 = v[j].z, w3 = v[j].w;
        unsigned r0 = run;
        unsigned r1 = r0 + __popc(w0);
        unsigned r2 = r1 + __popc(w1);
        unsigned r3 = r2 + __popc(w2);
        run = r3 + __popc(w3);
        dst[2 * j + 0] = make_uint4(w0, r0, w1, r1);
        dst[2 * j + 1] = make_uint4(w2, r2, w3, r3);
    }
}

// ------------- pass 2: full_coors (raw) + inverse, FLOAT32 output
__global__ __launch_bounds__(256) void k2(float* __restrict__ out, int n) {
    int i = blockIdx.x * 256 + threadIdx.x;
    if (i >= n) return;
    unsigned r = g_pt[i];
    unsigned b  = r >> 27;
    unsigned x1 = (r >> 17) & 1023u;
    unsigned y1 = (r >> 7) & 1023u;
    unsigned z1 = r & 127u;
#pragma unroll
    for (int s = 0; s < 4; s++) {
        int k = c_k[s], xb = 9 - k, zb = 6 - k;
        unsigned xs = x1 >> k, ys = y1 >> k, zs = z1 >> k;   // raw per-scale
        unsigned key = (((((b << xb) + xs) << xb) + ys) << zb) + zs;
        uint2 mp = ((const uint2*)g_mp4)[c_woff[s] + (key >> 5)];
        unsigned inv = mp.y + __popc(mp.x & ((1u << (key & 31)) - 1u));
        float* fc = out + g_bases[3 * s + 0] + 4ll * i;
        *(float4*)fc = make_float4((float)b, (float)xs, (float)ys, (float)zs);
        out[g_bases[3 * s + 1] + i] = (float)inv;
    }
}

// ---------- pass 3: enumerate set bits -> coors rows [b,z,y,x], FLOAT32
// power-of-2 mod/div decode == reference's %,// (handles carried keys)
__global__ __launch_bounds__(256) void k3(int s, float* __restrict__ out) {
    unsigned w = blockIdx.x * 256u + threadIdx.x;  // word index within scale
    uint2 mp = ((const uint2*)g_mp4)[c_woff[s] + w];
    unsigned m = mp.x;
    if (!m) return;
    long long pr = (long long)mp.y;
    long long cob = g_bases[3 * s + 2];
    int k = c_k[s], xb = 9 - k, zb = 6 - k;
    unsigned wk = w << 5;
    while (m) {
        int bit = __ffs(m) - 1;
        m &= m - 1;
        unsigned key = wk | (unsigned)bit;
        unsigned z = key & ((1u << zb) - 1);
        unsigned y = (key >> zb) & ((1u << xb) - 1);
        unsigned x = (key >> (zb + xb)) & ((1u << xb) - 1);
        unsigned b = key >> (zb + 2 * xb);
        *(float4*)(out + cob + 4ll * pr) =
            make_float4((float)b, (float)z, (float)y, (float)x);
        pr++;
    }
}

// ---------------------------------------------------------------------------
extern "C" void kernel_launch(void* const* d_in, const int* in_sizes, int n_in,
                              void* d_out, int out_size) {
    // order auto-detect: points has 3x the elements of batch_idx
    const float* pts;
    const void*  bat;
    int n;
    if ((long long)in_sizes[0] == 3ll * in_sizes[1]) {
        pts = (const float*)d_in[0]; bat = d_in[1]; n = in_sizes[1];
    } else {
        pts = (const float*)d_in[1]; bat = d_in[0]; n = in_sizes[0];
    }

    kdetect<<<1, 1>>>((const unsigned*)bat);
    kzero<<<(TOTAL_WORDS / 4 + 255) / 256, 256>>>();
    k1<<<(n + 255) / 256, 256>>>(pts, bat, n);
    const int nb[4] = {65, 9, 2, 513};
    for (int s = 0; s < 4; s++) p1<<<nb[s], 256>>>(s);
    p2<<<1, 1024>>>(n);
    for (int s = 0; s < 4; s++) p3<<<nb[s], 256>>>(s);
    k2<<<(n + 255) / 256, 256>>>((float*)d_out, n);
    for (int s = 0; s < 4; s++) k3<<<nb[s] * 32, 256>>>(s, (float*)d_out);
}

// round 9
// speedup vs baseline: 1.1953x; 1.1953x over previous
#include <cuda_runtime.h>
#include <cstdint>

// ---------------------------------------------------------------------------
// voxelization, scales (2,4,8,1). JIT/XLA-folded f32 quantization:
//   idx = trunc((p - lo) * RN(dims/(hi-lo))), folded consts exact: 5.0f, 10.0f
//   idx_s = idx_1 >> k exactly; idx may equal dims (boundary carries).
//   key = ((b*S+x)*S+y)*Z+z via ADDITION (carry-exact vs reference int64).
// Output: single FLOAT32 buffer, per scale:
//   full_coors [N,4] (b,x,y,z raw) | inv [N] | coors [M,4] (b,z,y,x)
// Dense bitmask + popcount prefix replaces sort/unique.
// R9: launch-fusion round. 16 kernels -> 5:
//   kzero(+detect+ctr), k1, p12 (p1 x4 + embedded scan), p3all, kout (k2+k3).
// ---------------------------------------------------------------------------

#define NMAX 2000000
// per-scale mask words padded past max carried key, in 8192-word blocks:
// scale2:65 scale4:9 scale8:2 scale1:513  (=589 blocks total)
#define TOTAL_WORDS 4825088   // 589*8192
#define NBLK_TOT 589

__device__ unsigned  g_mask[TOTAL_WORDS];            // 19.3 MB bitmasks
__device__ uint4     g_mp4[TOTAL_WORDS / 2];         // 38.6 MB {mask,prefix}
__device__ unsigned  g_pt[NMAX];                     // 8 MB packed b,x1,y1,z1
__device__ unsigned  g_blocksum[4 * 1024];
__device__ long long g_bases[12];                    // ELEMENT offs: fc,inv,coors
__device__ int       g_is64;                         // batch INPUT width only
__device__ unsigned  g_ctr;                          // p12 completion counter

__constant__ int      c_k[4]    = {1, 2, 3, 0};
__constant__ unsigned c_woff[4] = {0u, 532480u, 606208u, 622592u};
__constant__ int      c_nb[4]   = {65, 9, 2, 513};

// blockIdx -> (scale, local block) for the 589-block region kernels
__device__ __forceinline__ void blk2scale(unsigned bid, int& s, unsigned& lb) {
    if (bid < 65u)      { s = 0; lb = bid; }
    else if (bid < 74u) { s = 1; lb = bid - 65u; }
    else if (bid < 76u) { s = 2; lb = bid - 74u; }
    else                { s = 3; lb = bid - 76u; }
}

// word index -> scale (for kout's enumeration half)
__device__ __forceinline__ int word2scale(unsigned w) {
    return (w < 532480u) ? 0 : (w < 606208u) ? 1 : (w < 622592u) ? 2 : 3;
}

// -------------------------------- zero masks + input-width detect + ctr reset
__global__ __launch_bounds__(256) void kzero(const unsigned* __restrict__ bat) {
    unsigned i = blockIdx.x * 256u + threadIdx.x;
    if (i < TOTAL_WORDS / 4) ((uint4*)g_mask)[i] = make_uint4(0u, 0u, 0u, 0u);
    if (i == 0) {
        g_ctr = 0u;
        // int64 batch values in [0,8): every odd 32-bit word is zero.
        unsigned acc = 0;
#pragma unroll
        for (int j = 1; j <= 16; j++) acc |= bat[2 * j + 1];
        g_is64 = (acc == 0u) ? 1 : 0;
    }
}

// -------------------------------------- pass 1: packed point + bitmask set
__global__ __launch_bounds__(256) void k1(const float* __restrict__ pts,
                                          const void* __restrict__ bat,
                                          int n) {
    int i = blockIdx.x * 256 + threadIdx.x;
    if (i >= n) return;
    float px = pts[3 * i + 0];
    float py = pts[3 * i + 1];
    float pz = pts[3 * i + 2];
    unsigned b;
    if (g_is64) b = (unsigned)((const long long*)bat)[i];
    else        b = (unsigned)((const int*)bat)[i];
    // JIT/XLA-folded f32: trunc((p-lo) * const); consts exact. idx may == dims.
    unsigned x1 = (unsigned)(int)__fmul_rn(__fsub_rn(px, -51.2f), 5.0f);
    unsigned y1 = (unsigned)(int)__fmul_rn(__fsub_rn(py, -51.2f), 5.0f);
    unsigned z1 = (unsigned)(int)__fmul_rn(__fsub_rn(pz, -4.0f), 10.0f);
    g_pt[i] = (b << 27) | (x1 << 17) | (y1 << 7) | z1;   // raw, incl. boundary
#pragma unroll
    for (int s = 0; s < 4; s++) {
        int k = c_k[s], xb = 9 - k, zb = 6 - k;
        unsigned key = (((((b << xb) + (x1 >> k)) << xb) + (y1 >> k)) << zb)
                       + (z1 >> k);
        unsigned w = c_woff[s] + (key >> 5), bm = 1u << (key & 31);
        if (!(g_mask[w] & bm)) atomicOr(&g_mask[w], bm);  // stale=subset: safe
    }
}

// block-wide inclusive scan of one value per thread (256 threads, 8 warps)
__device__ __forceinline__ unsigned blockscan256(unsigned v, unsigned* shw,
                                                 int tid) {
    unsigned x = v;
#pragma unroll
    for (int o = 1; o < 32; o <<= 1) {
        unsigned t = __shfl_up_sync(0xffffffffu, x, o);
        if ((tid & 31) >= o) x += t;
    }
    if ((tid & 31) == 31) shw[tid >> 5] = x;
    __syncthreads();
    if (tid < 8) {
        unsigned y = shw[tid];
#pragma unroll
        for (int o = 1; o < 8; o <<= 1) {
            unsigned t = __shfl_up_sync(0xffu, y, o);
            if (tid >= o) y += t;
        }
        shw[tid] = y;
    }
    __syncthreads();
    unsigned add = (tid >= 32) ? shw[(tid >> 5) - 1] : 0u;
    return x + add;
}

// ---- p12: per-block popcount sums for ALL scales; last block scans + bases
__global__ __launch_bounds__(256) void p12(int n) {
    int s; unsigned lb;
    blk2scale(blockIdx.x, s, lb);
    int tid = threadIdx.x;
    unsigned base = c_woff[s] + lb * 8192u + tid * 32u;
    const uint4* src = (const uint4*)(g_mask + base);
    unsigned sum = 0;
#pragma unroll
    for (int j = 0; j < 8; j++) {
        uint4 v = src[j];
        sum += __popc(v.x) + __popc(v.y) + __popc(v.z) + __popc(v.w);
    }
    __shared__ unsigned sh[256];
    sh[tid] = sum;
    __syncthreads();
    for (int o = 128; o; o >>= 1) {
        if (tid < o) sh[tid] += sh[tid + o];
        __syncthreads();
    }
    __shared__ unsigned s_last;
    if (tid == 0) {
        g_blocksum[s * 1024 + lb] = sh[0];
        __threadfence();
        s_last = (atomicAdd(&g_ctr, 1u) == NBLK_TOT - 1u) ? 1u : 0u;
    }
    __syncthreads();
    if (!s_last) return;

    // ---- last block: scan block sums per scale, compute section bases ----
    __shared__ unsigned shw[8];
    __shared__ unsigned s_tot;
    __shared__ unsigned Mtot[4];
    for (int sc = 0; sc < 4; sc++) {
        int nb = c_nb[sc];
        unsigned carry = 0;
        for (int cb = 0; cb < nb; cb += 256) {
            int idx = cb + tid;
            unsigned v = (idx < nb) ? g_blocksum[sc * 1024 + idx] : 0u;
            unsigned inc = blockscan256(v, shw, tid);
            if (idx < nb) g_blocksum[sc * 1024 + idx] = carry + inc - v;
            if (tid == 255) s_tot = inc;
            __syncthreads();
            carry += s_tot;
            __syncthreads();
        }
        if (tid == 0) Mtot[sc] = carry;
    }
    __syncthreads();
    if (tid == 0) {
        long long base2 = 0;  // float-element offsets into d_out
        for (int sc = 0; sc < 4; sc++) {
            g_bases[3 * sc + 0] = base2;                // full_coors (4n)
            g_bases[3 * sc + 1] = base2 + 4ll * n;      // inv (n)
            g_bases[3 * sc + 2] = base2 + 5ll * n;      // coors (4M)
            base2 += 5ll * n + 4ll * (long long)Mtot[sc];
        }
    }
}

// ------ p3all: word-level exclusive prefix, write {mask,prefix} pairs
__global__ __launch_bounds__(256) void p3all() {
    int s; unsigned lb;
    blk2scale(blockIdx.x, s, lb);
    int tid = threadIdx.x;
    unsigned wbase = c_woff[s] + lb * 8192u + tid * 32u;
    const uint4* src = (const uint4*)(g_mask + wbase);
    uint4 v[8];
    unsigned sum = 0;
#pragma unroll
    for (int j = 0; j < 8; j++) v[j] = src[j];
#pragma unroll
    for (int j = 0; j < 8; j++)
        sum += __popc(v[j].x) + __popc(v[j].y) + __popc(v[j].z) + __popc(v[j].w);
    __shared__ unsigned shw[8];
    unsigned incl = blockscan256(sum, shw, tid);
    unsigned run = g_blocksum[s * 1024 + lb] + incl - sum;
    uint4* dst = (uint4*)((uint2*)g_mp4 + wbase);
#pragma unroll
    for (int j = 0; j < 8; j++) {
        unsigned w0 = v[j].x, w1 = v[j].y, w2 = v[j].z, w3 = v[j].w;
        unsigned r0 = run;
        unsigned r1 = r0 + __popc(w0);
        unsigned r2 = r1 + __popc(w1);
        unsigned r3 = r2 + __popc(w2);
        run = r3 + __popc(w3);
        dst[2 * j + 0] = make_uint4(w0, r0, w1, r1);
        dst[2 * j + 1] = make_uint4(w2, r2, w3, r3);
    }
}

// ---- kout: blocks [0,nb2) = per-point outputs (full_coors + inv);
//      blocks [nb2, ...)    = unique enumeration (coors). FLOAT32 out.
__global__ __launch_bounds__(256) void kout(float* __restrict__ out, int n,
                                            int nb2) {
    if ((int)blockIdx.x < nb2) {
        int i = blockIdx.x * 256 + threadIdx.x;
        if (i >= n) return;
        unsigned r = g_pt[i];
        unsigned b  = r >> 27;
        unsigned x1 = (r >> 17) & 1023u;
        unsigned y1 = (r >> 7) & 1023u;
        unsigned z1 = r & 127u;
#pragma unroll
        for (int s = 0; s < 4; s++) {
            int k = c_k[s], xb = 9 - k, zb = 6 - k;
            unsigned xs = x1 >> k, ys = y1 >> k, zs = z1 >> k;
            unsigned key = (((((b << xb) + xs) << xb) + ys) << zb) + zs;
            uint2 mp = ((const uint2*)g_mp4)[c_woff[s] + (key >> 5)];
            unsigned inv = mp.y + __popc(mp.x & ((1u << (key & 31)) - 1u));
            float* fc = out + g_bases[3 * s + 0] + 4ll * i;
            *(float4*)fc = make_float4((float)b, (float)xs, (float)ys, (float)zs);
            out[g_bases[3 * s + 1] + i] = (float)inv;
        }
    } else {
        unsigned w = (blockIdx.x - nb2) * 256u + threadIdx.x;
        if (w >= TOTAL_WORDS) return;
        uint2 mp = ((const uint2*)g_mp4)[w];
        unsigned m = mp.x;
        if (!m) return;
        int s = word2scale(w);
        long long pr = (long long)mp.y;
        long long cob = g_bases[3 * s + 2];
        int k = c_k[s], xb = 9 - k, zb = 6 - k;
        unsigned wk = (w - c_woff[s]) << 5;
        while (m) {
            int bit = __ffs(m) - 1;
            m &= m - 1;
            unsigned key = wk | (unsigned)bit;
            unsigned z = key & ((1u << zb) - 1);
            unsigned y = (key >> zb) & ((1u << xb) - 1);
            unsigned x = (key >> (zb + xb)) & ((1u << xb) - 1);
            unsigned b = key >> (zb + 2 * xb);
            *(float4*)(out + cob + 4ll * pr) =
                make_float4((float)b, (float)z, (float)y, (float)x);
            pr++;
        }
    }
}

// ---------------------------------------------------------------------------
extern "C" void kernel_launch(void* const* d_in, const int* in_sizes, int n_in,
                              void* d_out, int out_size) {
    // order auto-detect: points has 3x the elements of batch_idx
    const float* pts;
    const void*  bat;
    int n;
    if ((long long)in_sizes[0] == 3ll * in_sizes[1]) {
        pts = (const float*)d_in[0]; bat = d_in[1]; n = in_sizes[1];
    } else {
        pts = (const float*)d_in[1]; bat = d_in[0]; n = in_sizes[0];
    }

    kzero<<<(TOTAL_WORDS / 4 + 255) / 256, 256>>>((const unsigned*)bat);
    k1<<<(n + 255) / 256, 256>>>(pts, bat, n);
    p12<<<NBLK_TOT, 256>>>(n);
    p3all<<<NBLK_TOT, 256>>>();
    int nb2 = (n + 255) / 256;
    int nb3 = (TOTAL_WORDS + 255) / 256;
    kout<<<nb2 + nb3, 256>>>((float*)d_out, n, nb2);
}

// round 10
// speedup vs baseline: 1.1994x; 1.0034x over previous
#include <cuda_runtime.h>
#include <cstdint>

// ---------------------------------------------------------------------------
// voxelization, scales (2,4,8,1). JIT/XLA-folded f32 quantization:
//   idx = trunc((p - lo) * RN(dims/(hi-lo))), folded consts exact: 5.0f, 10.0f
//   idx_s = idx_1 >> k exactly; idx may equal dims (boundary carries).
//   key = ((b*S+x)*S+y)*Z+z via ADDITION (carry-exact vs reference int64).
// Output: single FLOAT32 buffer, per scale:
//   full_coors [N,4] (b,x,y,z raw) | inv [N] | coors [M,4] (b,z,y,x)
// Dense bitmask + popcount prefix replaces sort/unique.
// R10: p12+p3all fused into ONE decoupled-lookback scan kernel (pscan):
//   one mask sweep instead of two, no serialized block-sum scan, 4 launches.
// ---------------------------------------------------------------------------

#define NMAX 2000000
// per-scale mask words padded past max carried key, in 8192-word blocks:
// scale2:65 scale4:9 scale8:2 scale1:513  (=589 blocks total)
#define TOTAL_WORDS 4825088   // 589*8192
#define NBLK_TOT 589

__device__ unsigned  g_mask[TOTAL_WORDS];            // 19.3 MB bitmasks
__device__ uint4     g_mp4[TOTAL_WORDS / 2];         // 38.6 MB {mask,prefix}
__device__ unsigned  g_pt[NMAX];                     // 8 MB packed b,x1,y1,z1
__device__ unsigned long long g_stat[NBLK_TOT];      // lookback: flag<<32 | sum
__device__ long long g_bases[12];                    // ELEMENT offs: fc,inv,coors
__device__ int       g_is64;                         // batch INPUT width only
__device__ unsigned  g_ctr;                          // pscan completion counter

__constant__ int      c_k[4]    = {1, 2, 3, 0};
__constant__ unsigned c_woff[4] = {0u, 532480u, 606208u, 622592u};
__constant__ int      c_nb[4]   = {65, 9, 2, 513};
__constant__ int      c_sb[4]   = {0, 65, 74, 76};   // scale start block

// blockIdx -> (scale, local block) for the 589-block region kernels
__device__ __forceinline__ void blk2scale(unsigned bid, int& s, unsigned& lb) {
    if (bid < 65u)      { s = 0; lb = bid; }
    else if (bid < 74u) { s = 1; lb = bid - 65u; }
    else if (bid < 76u) { s = 2; lb = bid - 74u; }
    else                { s = 3; lb = bid - 76u; }
}

// word index -> scale (for kout's enumeration half)
__device__ __forceinline__ int word2scale(unsigned w) {
    return (w < 532480u) ? 0 : (w < 606208u) ? 1 : (w < 622592u) ? 2 : 3;
}

// ---------------- zero masks + lookback state + input-width detect
__global__ __launch_bounds__(256) void kzero(const unsigned* __restrict__ bat) {
    unsigned i = blockIdx.x * 256u + threadIdx.x;
    if (i < TOTAL_WORDS / 4) ((uint4*)g_mask)[i] = make_uint4(0u, 0u, 0u, 0u);
    if (blockIdx.x == 0) {
        for (int j = threadIdx.x; j < NBLK_TOT; j += 256) g_stat[j] = 0ull;
        if (threadIdx.x == 0) {
            g_ctr = 0u;
            // int64 batch values in [0,8): every odd 32-bit word is zero.
            unsigned acc = 0;
#pragma unroll
            for (int j = 1; j <= 16; j++) acc |= bat[2 * j + 1];
            g_is64 = (acc == 0u) ? 1 : 0;
        }
    }
}

// -------------------------------------- pass 1: packed point + bitmask set
__global__ __launch_bounds__(256) void k1(const float* __restrict__ pts,
                                          const void* __restrict__ bat,
                                          int n) {
    int i = blockIdx.x * 256 + threadIdx.x;
    if (i >= n) return;
    float px = pts[3 * i + 0];
    float py = pts[3 * i + 1];
    float pz = pts[3 * i + 2];
    unsigned b;
    if (g_is64) b = (unsigned)((const long long*)bat)[i];
    else        b = (unsigned)((const int*)bat)[i];
    // JIT/XLA-folded f32: trunc((p-lo) * const); consts exact. idx may == dims.
    unsigned x1 = (unsigned)(int)__fmul_rn(__fsub_rn(px, -51.2f), 5.0f);
    unsigned y1 = (unsigned)(int)__fmul_rn(__fsub_rn(py, -51.2f), 5.0f);
    unsigned z1 = (unsigned)(int)__fmul_rn(__fsub_rn(pz, -4.0f), 10.0f);
    g_pt[i] = (b << 27) | (x1 << 17) | (y1 << 7) | z1;   // raw, incl. boundary
#pragma unroll
    for (int s = 0; s < 4; s++) {
        int k = c_k[s], xb = 9 - k, zb = 6 - k;
        unsigned key = (((((b << xb) + (x1 >> k)) << xb) + (y1 >> k)) << zb)
                       + (z1 >> k);
        unsigned w = c_woff[s] + (key >> 5), bm = 1u << (key & 31);
        if (!(g_mask[w] & bm)) atomicOr(&g_mask[w], bm);  // stale=subset: safe
    }
}

// block-wide inclusive scan of one value per thread (256 threads, 8 warps)
__device__ __forceinline__ unsigned blockscan256(unsigned v, unsigned* shw,
                                                 int tid) {
    unsigned x = v;
#pragma unroll
    for (int o = 1; o < 32; o <<= 1) {
        unsigned t = __shfl_up_sync(0xffffffffu, x, o);
        if ((tid & 31) >= o) x += t;
    }
    if ((tid & 31) == 31) shw[tid >> 5] = x;
    __syncthreads();
    if (tid < 8) {
        unsigned y = shw[tid];
#pragma unroll
        for (int o = 1; o < 8; o <<= 1) {
            unsigned t = __shfl_up_sync(0xffu, y, o);
            if (tid >= o) y += t;
        }
        shw[tid] = y;
    }
    __syncthreads();
    unsigned add = (tid >= 32) ? shw[(tid >> 5) - 1] : 0u;
    return x + add;
}

// ---- pscan: single-pass popcount scan (decoupled lookback, per scale) +
//      {mask, prefix} pair emission + section-base computation (last block).
__global__ __launch_bounds__(256) void pscan(int n) {
    int s; unsigned lb;
    blk2scale(blockIdx.x, s, lb);
    int tid = threadIdx.x;
    unsigned wbase = c_woff[s] + lb * 8192u + tid * 32u;
    const uint4* src = (const uint4*)(g_mask + wbase);
    // phase A: popcount local slice (values reloaded later from L1)
    unsigned sum = 0;
#pragma unroll
    for (int j = 0; j < 8; j++) {
        uint4 v = src[j];
        sum += __popc(v.x) + __popc(v.y) + __popc(v.z) + __popc(v.w);
    }
    __shared__ unsigned shw[8];
    unsigned incl = blockscan256(sum, shw, tid);
    __shared__ unsigned s_agg, s_base;
    if (tid == 255) s_agg = incl;
    __syncthreads();
    if (tid == 0) {
        unsigned agg = s_agg, excl = 0;
        if (lb == 0) {
            atomicExch(&g_stat[blockIdx.x], (2ull << 32) | agg);
        } else {
            atomicExch(&g_stat[blockIdx.x], (1ull << 32) | agg);
            int j = (int)blockIdx.x - 1;
            int sstart = (int)blockIdx.x - (int)lb;
            while (j >= sstart) {
                unsigned long long st;
                do { st = atomicAdd(&g_stat[j], 0ull); } while ((st >> 32) == 0ull);
                excl += (unsigned)st;
                if ((st >> 32) == 2ull) break;
                j--;
            }
            atomicExch(&g_stat[blockIdx.x], (2ull << 32) | (excl + agg));
        }
        s_base = excl;
    }
    __syncthreads();
    // phase B: emit {mask, prefix} pairs (mask reloaded, L1-resident)
    unsigned run = s_base + incl - sum;
    uint4* dst = (uint4*)((uint2*)g_mp4 + wbase);
#pragma unroll
    for (int j = 0; j < 8; j++) {
        uint4 v = src[j];
        unsigned r0 = run;
        unsigned r1 = r0 + __popc(v.x);
        unsigned r2 = r1 + __popc(v.y);
        unsigned r3 = r2 + __popc(v.z);
        run = r3 + __popc(v.w);
        dst[2 * j + 0] = make_uint4(v.x, r0, v.y, r1);
        dst[2 * j + 1] = make_uint4(v.z, r2, v.w, r3);
    }
    // last-arriving block computes output section bases
    __syncthreads();
    if (tid == 0) {
        __threadfence();
        if (atomicAdd(&g_ctr, 1u) == NBLK_TOT - 1u) {
            long long base2 = 0;  // float-element offsets into d_out
            for (int sc = 0; sc < 4; sc++) {
                int lastb = c_sb[sc] + c_nb[sc] - 1;
                unsigned Mtot = (unsigned)atomicAdd(&g_stat[lastb], 0ull);
                g_bases[3 * sc + 0] = base2;             // full_coors (4n)
                g_bases[3 * sc + 1] = base2 + 4ll * n;   // inv (n)
                g_bases[3 * sc + 2] = base2 + 5ll * n;   // coors (4M)
                base2 += 5ll * n + 4ll * (long long)Mtot;
            }
        }
    }
}

// ---- kout: blocks [0,nb2) = per-point outputs (full_coors + inv);
//      blocks [nb2, ...)    = unique enumeration (coors). FLOAT32 out.
__global__ __launch_bounds__(256) void kout(float* __restrict__ out, int n,
                                            int nb2) {
    if ((int)blockIdx.x < nb2) {
        int i = blockIdx.x * 256 + threadIdx.x;
        if (i >= n) return;
        unsigned r = g_pt[i];
        unsigned b  = r >> 27;
        unsigned x1 = (r >> 17) & 1023u;
        unsigned y1 = (r >> 7) & 1023u;
        unsigned z1 = r & 127u;
#pragma unroll
        for (int s = 0; s < 4; s++) {
            int k = c_k[s], xb = 9 - k, zb = 6 - k;
            unsigned xs = x1 >> k, ys = y1 >> k, zs = z1 >> k;
            unsigned key = (((((b << xb) + xs) << xb) + ys) << zb) + zs;
            uint2 mp = ((const uint2*)g_mp4)[c_woff[s] + (key >> 5)];
            unsigned inv = mp.y + __popc(mp.x & ((1u << (key & 31)) - 1u));
            float* fc = out + g_bases[3 * s + 0] + 4ll * i;
            *(float4*)fc = make_float4((float)b, (float)xs, (float)ys, (float)zs);
            out[g_bases[3 * s + 1] + i] = (float)inv;
        }
    } else {
        unsigned w = (blockIdx.x - nb2) * 256u + threadIdx.x;
        if (w >= TOTAL_WORDS) return;
        uint2 mp = ((const uint2*)g_mp4)[w];
        unsigned m = mp.x;
        if (!m) return;
        int s = word2scale(w);
        long long pr = (long long)mp.y;
        long long cob = g_bases[3 * s + 2];
        int k = c_k[s], xb = 9 - k, zb = 6 - k;
        unsigned wk = (w - c_woff[s]) << 5;
        while (m) {
            int bit = __ffs(m) - 1;
            m &= m - 1;
            unsigned key = wk | (unsigned)bit;
            unsigned z = key & ((1u << zb) - 1);
            unsigned y = (key >> zb) & ((1u << xb) - 1);
            unsigned x = (key >> (zb + xb)) & ((1u << xb) - 1);
            unsigned b = key >> (zb + 2 * xb);
            *(float4*)(out + cob + 4ll * pr) =
                make_float4((float)b, (float)z, (float)y, (float)x);
            pr++;
        }
    }
}

// ---------------------------------------------------------------------------
extern "C" void kernel_launch(void* const* d_in, const int* in_sizes, int n_in,
                              void* d_out, int out_size) {
    // order auto-detect: points has 3x the elements of batch_idx
    const float* pts;
    const void*  bat;
    int n;
    if ((long long)in_sizes[0] == 3ll * in_sizes[1]) {
        pts = (const float*)d_in[0]; bat = d_in[1]; n = in_sizes[1];
    } else {
        pts = (const float*)d_in[1]; bat = d_in[0]; n = in_sizes[0];
    }

    kzero<<<(TOTAL_WORDS / 4 + 255) / 256, 256>>>((const unsigned*)bat);
    k1<<<(n + 255) / 256, 256>>>(pts, bat, n);
    pscan<<<NBLK_TOT, 256>>>(n);
    int nb2 = (n + 255) / 256;
    int nb3 = (TOTAL_WORDS + 255) / 256;
    kout<<<nb2 + nb3, 256>>>((float*)d_out, n, nb2);
}